// round 14
// baseline (speedup 1.0000x reference)
#include <cuda_runtime.h>
#include <cuda_bf16.h>
#include <math.h>
#include <stdint.h>

#define B_ 2
#define S_ 2048
#define E_ 1024
#define H_ 16
#define DH 64

// Scratch (device globals — no allocation allowed)
__device__ __nv_bfloat16 g_xh[(size_t)B_ * S_ * E_];
__device__ __nv_bfloat16 g_xl[(size_t)B_ * S_ * E_];
__device__ __nv_bfloat16 g_Wqh[(size_t)E_ * E_];
__device__ __nv_bfloat16 g_Wql[(size_t)E_ * E_];
__device__ __nv_bfloat16 g_Wvh[(size_t)E_ * E_];
__device__ __nv_bfloat16 g_Wvl[(size_t)E_ * E_];
__device__ __nv_bfloat16 g_Qh[(size_t)B_ * H_ * S_ * DH];
__device__ __nv_bfloat16 g_Ql[(size_t)B_ * H_ * S_ * DH];
__device__ __nv_bfloat16 g_Vh[(size_t)B_ * H_ * S_ * DH];
__device__ __nv_bfloat16 g_Vl[(size_t)B_ * H_ * S_ * DH];
__device__ float g_Whp[(size_t)E_ * 96];     // [e][h*6+n]
__device__ float g_cbias[96];
__device__ int   g_bkt[B_ * H_ * S_];

typedef unsigned long long u64;
union F2 { u64 u; float2 f; };

__device__ __forceinline__ u64 dup2(float x) {
    u64 r; asm("mov.b64 %0,{%1,%1};" : "=l"(r) : "f"(x)); return r;
}
__device__ __forceinline__ void fma2(u64& d, u64 a, u64 b) {
    asm("fma.rn.f32x2 %0,%1,%2,%3;" : "=l"(d) : "l"(a), "l"(b), "l"(d));
}
__device__ __forceinline__ void ldsm4(uint32_t* r, uint32_t a) {
    asm volatile("ldmatrix.sync.aligned.m8n8.x4.shared.b16 {%0,%1,%2,%3},[%4];"
                 : "=r"(r[0]), "=r"(r[1]), "=r"(r[2]), "=r"(r[3]) : "r"(a));
}
__device__ __forceinline__ void ldsm4t(uint32_t* r, uint32_t a) {
    asm volatile("ldmatrix.sync.aligned.m8n8.x4.trans.shared.b16 {%0,%1,%2,%3},[%4];"
                 : "=r"(r[0]), "=r"(r[1]), "=r"(r[2]), "=r"(r[3]) : "r"(a));
}
__device__ __forceinline__ void mma16816(float* c, const uint32_t* a,
                                         uint32_t b0, uint32_t b1) {
    asm volatile(
        "mma.sync.aligned.m16n8k16.row.col.f32.bf16.bf16.f32 "
        "{%0,%1,%2,%3},{%4,%5,%6,%7},{%8,%9},{%0,%1,%2,%3};"
        : "+f"(c[0]), "+f"(c[1]), "+f"(c[2]), "+f"(c[3])
        : "r"(a[0]), "r"(a[1]), "r"(a[2]), "r"(a[3]), "r"(b0), "r"(b1));
}
__device__ __forceinline__ uint32_t packbf(float lo, float hi) {
    uint32_t r; asm("cvt.rn.bf16x2.f32 %0,%1,%2;" : "=r"(r) : "f"(hi), "f"(lo));
    return r;
}
__device__ __forceinline__ void cpa16(uint32_t dst, const void* src) {
    asm volatile("cp.async.cg.shared.global [%0],[%1],16;" :: "r"(dst), "l"(src));
}
__device__ __forceinline__ void cpa4(uint32_t dst, const void* src) {
    asm volatile("cp.async.ca.shared.global [%0],[%1],4;" :: "r"(dst), "l"(src));
}
#define CP_COMMIT() asm volatile("cp.async.commit_group;")
template <int N>
__device__ __forceinline__ void cp_wait() {
    asm volatile("cp.async.wait_group %0;" :: "n"(N));
}

// ---------------------------------------------------------------------------
// Split x, Wq, Wv into bf16 hi/lo pairs. 4 floats per thread.
// ---------------------------------------------------------------------------
__global__ __launch_bounds__(256)
void split_kernel(const float* __restrict__ x, const float* __restrict__ Wq,
                  const float* __restrict__ Wv)
{
    size_t idx4 = (size_t)blockIdx.x * 256 + threadIdx.x;
    size_t flat = idx4 * 4;
    const float* src; __nv_bfloat16* dh; __nv_bfloat16* dl; size_t off;
    const size_t NX = (size_t)B_ * S_ * E_;
    const size_t NW = (size_t)E_ * E_;
    if (flat < NX)            { src = x;  dh = g_xh;  dl = g_xl;  off = flat; }
    else if (flat < NX + NW)  { src = Wq; dh = g_Wqh; dl = g_Wql; off = flat - NX; }
    else                      { src = Wv; dh = g_Wvh; dl = g_Wvl; off = flat - NX - NW; }

    float4 v = *(const float4*)(src + off);
    float vv[4] = {v.x, v.y, v.z, v.w};
    __align__(8) __nv_bfloat16 hi[4], lo[4];
#pragma unroll
    for (int j = 0; j < 4; j++) {
        hi[j] = __float2bfloat16(vv[j]);
        lo[j] = __float2bfloat16(vv[j] - __bfloat162float(hi[j]));
    }
    *(uint2*)(dh + off) = *(const uint2*)hi;
    *(uint2*)(dl + off) = *(const uint2*)lo;
}

// ---------------------------------------------------------------------------
// Whp[e][h*6+n] = sum_d Wq[h*64+d][e] * hp[d][n]  ;  cbias[hn] too.
// ---------------------------------------------------------------------------
__global__ __launch_bounds__(256)
void whp_kernel(const float* __restrict__ Wq, const float* __restrict__ bq,
                const float* __restrict__ hp)
{
    const int hn = blockIdx.y;
    const int h = hn / 6, n = hn % 6;
    const int e = blockIdx.x * 256 + threadIdx.x;
    float acc = 0.f;
#pragma unroll 8
    for (int d = 0; d < 64; d++)
        acc = fmaf(Wq[(size_t)(h * 64 + d) * E_ + e], __ldg(hp + d * 6 + n), acc);
    g_Whp[(size_t)e * 96 + hn] = acc;
    if (blockIdx.x == 0 && threadIdx.x == 0) {
        float cb = hp[64 * 6 + n];
        for (int d = 0; d < 64; d++)
            cb = fmaf(bq[h * 64 + d], hp[d * 6 + n], cb);
        g_cbias[hn] = cb;
    }
}

// ---------------------------------------------------------------------------
// Bucket GEMM (fp32 f32x2): proj[m][hn] = x @ Whp + cbias; sign bits.
// ---------------------------------------------------------------------------
#define BK_B 128
__global__ __launch_bounds__(256)
void bucket_kernel(const float* __restrict__ x)
{
    extern __shared__ float bsm[];
    float* sx = bsm;                 // [BK_B][68]
    float* sw = bsm + BK_B * 68;     // [BK_B][96]

    const int tid = threadIdx.x;
    const int tx = tid & 31;
    const int ty = tid >> 5;
    const int m0 = blockIdx.x * 64;

    u64 acc[4][3];
#pragma unroll
    for (int p = 0; p < 4; p++)
#pragma unroll
        for (int c = 0; c < 3; c++) acc[p][c] = dup2(g_cbias[tx + 32 * c]);

    for (int k0 = 0; k0 < E_; k0 += BK_B) {
#pragma unroll
        for (int it = 0; it < 8; it++) {
            int idx = it * 256 + tid;
            int r = idx >> 5;
            int c4 = (idx & 31) << 2;
            float4 v = *(const float4*)(x + (size_t)(m0 + r) * E_ + k0 + c4);
            sx[(c4 + 0) * 68 + r] = v.x; sx[(c4 + 1) * 68 + r] = v.y;
            sx[(c4 + 2) * 68 + r] = v.z; sx[(c4 + 3) * 68 + r] = v.w;
        }
#pragma unroll
        for (int it = 0; it < 12; it++) {
            int u4 = it * 256 + tid;
            *(uint4*)(sw + u4 * 4) =
                *(const uint4*)(g_Whp + (size_t)k0 * 96 + u4 * 4);
        }
        __syncthreads();

#pragma unroll 4
        for (int k = 0; k < BK_B; k++) {
            ulonglong2 x01 = *(const ulonglong2*)(sx + k * 68 + 8 * ty);
            ulonglong2 x23 = *(const ulonglong2*)(sx + k * 68 + 8 * ty + 4);
            u64 xp[4] = {x01.x, x01.y, x23.x, x23.y};
            u64 w0 = dup2(sw[k * 96 + tx]);
            u64 w1 = dup2(sw[k * 96 + tx + 32]);
            u64 w2 = dup2(sw[k * 96 + tx + 64]);
#pragma unroll
            for (int p = 0; p < 4; p++) {
                fma2(acc[p][0], xp[p], w0);
                fma2(acc[p][1], xp[p], w1);
                fma2(acc[p][2], xp[p], w2);
            }
        }
        __syncthreads();
    }

    float* sproj = sx;
#pragma unroll
    for (int p = 0; p < 4; p++) {
#pragma unroll
        for (int c = 0; c < 3; c++) {
            F2 u; u.u = acc[p][c];
            sproj[(8 * ty + 2 * p) * 96 + tx + 32 * c]     = u.f.x;
            sproj[(8 * ty + 2 * p + 1) * 96 + tx + 32 * c] = u.f.y;
        }
    }
    __syncthreads();

#pragma unroll
    for (int u = 0; u < 4; u++) {
        int o = u * 256 + tid;
        int row = o >> 4, h = o & 15;
        int bucket = 0;
#pragma unroll
        for (int n = 0; n < 6; n++)
            if (sproj[row * 96 + h * 6 + n] >= 0.f) bucket |= (1 << n);
        int m = m0 + row;
        int b = m >> 11, s = m & (S_ - 1);
        g_bkt[(b * H_ + h) * S_ + s] = bucket;
    }
}

// ---------------------------------------------------------------------------
// Tensor-core projection GEMM (bf16 x3, mma.sync), 2-stage cp.async pipeline.
// (unchanged — measured at the legacy-HMMA ceiling)
// ---------------------------------------------------------------------------
#define PST 40
#define PJ_TILE_B (128 * PST * 2)          // 10240 B per array
#define PJ_STAGE_B (4 * PJ_TILE_B)         // 40960 B per stage

__global__ __launch_bounds__(256, 2)
void proj_tc_kernel(const float* __restrict__ bq, const float* __restrict__ bv)
{
    extern __shared__ char psm[];
    const uint32_t aS = (uint32_t)__cvta_generic_to_shared(psm);

    const int z = blockIdx.z;
    const __nv_bfloat16* Bh_g = z ? g_Wvh : g_Wqh;
    const __nv_bfloat16* Bl_g = z ? g_Wvl : g_Wql;
    const float* bias = z ? bv : bq;
    __nv_bfloat16* Hh = z ? g_Vh : g_Qh;
    __nv_bfloat16* Hl = z ? g_Vl : g_Ql;

    const int tid = threadIdx.x;
    const int wid = tid >> 5, lane = tid & 31;
    const int qid = lane >> 2, l2 = lane & 3;
    const int sel = lane >> 3, l7 = lane & 7;
    const int wm = wid & 3, wn = wid >> 2;
    const int m0 = blockIdx.y << 7;
    const int n0 = blockIdx.x << 7;

    const int r_ld[2]  = { (tid * 2) >> 2, (tid * 2 + 1) >> 2 };
    const int cu_ld[2] = { ((tid * 2) & 3) << 3, ((tid * 2 + 1) & 3) << 3 };

    float C[2][8][4];
#pragma unroll
    for (int a = 0; a < 2; a++)
#pragma unroll
        for (int j = 0; j < 8; j++)
#pragma unroll
            for (int t = 0; t < 4; t++) C[a][j][t] = 0.f;

    const uint32_t aoff = (uint32_t)((wm * 32 + (sel & 1) * 8 + l7) * (PST * 2)
                                     + (sel >> 1) * 16);
    const uint32_t bhl = (sel < 2) ? (2 * PJ_TILE_B) : (3 * PJ_TILE_B);
    const uint32_t boff = bhl + (wn * 64 + l7) * (PST * 2) + (sel & 1) * 16;

    auto prefetch = [&](int st, int k0) {
#pragma unroll
        for (int p = 0; p < 2; p++) {
            int r = r_ld[p], cu = cu_ld[p];
            size_t gx = (size_t)(m0 + r) * E_ + k0 + cu;
            size_t gw = (size_t)(n0 + r) * E_ + k0 + cu;
            uint32_t so = aS + st * PJ_STAGE_B + (r * PST + cu) * 2;
            cpa16(so,                 g_xh + gx);
            cpa16(so + PJ_TILE_B,     g_xl + gx);
            cpa16(so + 2 * PJ_TILE_B, Bh_g + gw);
            cpa16(so + 3 * PJ_TILE_B, Bl_g + gw);
        }
    };

    prefetch(0, 0);
    CP_COMMIT();

    for (int kt = 0; kt < 32; kt++) {
        if (kt + 1 < 32) {
            prefetch((kt + 1) & 1, (kt + 1) * 32);
            CP_COMMIT();
            cp_wait<1>();
        } else {
            cp_wait<0>();
        }
        __syncthreads();

        const uint32_t stB = aS + (kt & 1) * PJ_STAGE_B;
#pragma unroll
        for (int kk = 0; kk < 2; kk++) {
            uint32_t Ahf[2][4], Alf[2][4];
#pragma unroll
            for (int a = 0; a < 2; a++) {
                uint32_t ra = stB + aoff + a * 16 * (PST * 2) + kk * 32;
                ldsm4(Ahf[a], ra);
                ldsm4(Alf[a], ra + PJ_TILE_B);
            }
#pragma unroll
            for (int j = 0; j < 8; j++) {
                uint32_t bb[4];
                ldsm4(bb, stB + boff + j * 8 * (PST * 2) + kk * 32);
#pragma unroll
                for (int a = 0; a < 2; a++) {
                    mma16816(C[a][j], Ahf[a], bb[0], bb[1]);
                    mma16816(C[a][j], Alf[a], bb[0], bb[1]);
                    mma16816(C[a][j], Ahf[a], bb[2], bb[3]);
                }
            }
        }
        __syncthreads();
    }

#pragma unroll
    for (int a = 0; a < 2; a++) {
        int mrow = m0 + wm * 32 + a * 16 + qid;
#pragma unroll
        for (int j = 0; j < 8; j++) {
            int n = n0 + wn * 64 + j * 8 + 2 * l2;
            int h = n >> 6, d = n & 63;
            float b0 = bias[n], b1 = bias[n + 1];
#pragma unroll
            for (int half = 0; half < 2; half++) {
                int m = mrow + half * 8;
                int b = m >> 11, s = m & (S_ - 1);
                size_t off = (((size_t)(b * H_ + h)) * S_ + s) * DH + d;
                float v0 = C[a][j][2 * half + 0] + b0;
                float v1 = C[a][j][2 * half + 1] + b1;
                uint32_t hi = packbf(v0, v1);
                float l0 = v0 - __uint_as_float(hi << 16);
                float l1 = v1 - __uint_as_float(hi & 0xFFFF0000u);
                *(uint32_t*)(Hh + off) = hi;
                *(uint32_t*)(Hl + off) = packbf(l0, l1);
            }
        }
    }
}

// ---------------------------------------------------------------------------
// Tensor-core flash attention, s-tile=128, 256 threads (8 warps), 2 CTAs/SM.
// 2-stage cp.async pipeline for 64-wide K/V t-tiles; exp2-folded coefficients.
// ---------------------------------------------------------------------------
#define RS 72
#define RSB 144
#define AT_TILE_B (64 * RS * 2)            // 9216 B
#define AT_STAGE_B (4 * AT_TILE_B)         // 36864 B
#define AT_BK_OFF (2 * AT_STAGE_B)         // 73728 B
#define AT_SMEM (AT_BK_OFF + 2 * 64 * 4)   // 74240 B (x2 = 148.5 KB/SM)
// coeff * log2(e):  (63/32)*log2e, (62/32)*log2e
#define CF_SAME 2.84030586f
#define CF_DIFF 2.79522164f

__global__ __launch_bounds__(256, 2)
void attn_kernel(float* __restrict__ out)
{
    extern __shared__ char asm_[];
    const uint32_t aS = (uint32_t)__cvta_generic_to_shared(asm_);
    int* bkArr = (int*)(asm_ + AT_BK_OFF);

    const int tid = threadIdx.x;
    const int wid = tid >> 5, lane = tid & 31;
    const int qid = lane >> 2;
    const int l2  = lane & 3;
    const int sel = lane >> 3, l7 = lane & 7;

    const int bh = blockIdx.y;
    const int b = bh >> 4, h = bh & 15;
    const int s0 = blockIdx.x << 7;           // 128 rows per CTA
    const __nv_bfloat16* Qh_g = g_Qh + (size_t)bh * S_ * DH;
    const __nv_bfloat16* Ql_g = g_Ql + (size_t)bh * S_ * DH;
    const __nv_bfloat16* Vh_g = g_Vh + (size_t)bh * S_ * DH;
    const __nv_bfloat16* Vl_g = g_Vl + (size_t)bh * S_ * DH;
    const int* bkp = g_bkt + bh * S_;

    // ---- stage 128 Q rows into stage-0's four sub-tile areas ----
    // rows 0-63: hi in Kh area, lo in Kl area; rows 64-127: hi in Vh, lo in Vl.
#pragma unroll
    for (int i = tid; i < 1024; i += 256) {
        int r = i >> 3, c = (i & 7) << 3;
        uint32_t half_off = (r < 64) ? 0u : (uint32_t)(2 * AT_TILE_B);
        int rl = r & 63;
        __nv_bfloat16* dsth = (__nv_bfloat16*)(asm_ + half_off) + rl * RS + c;
        __nv_bfloat16* dstl = (__nv_bfloat16*)(asm_ + half_off + AT_TILE_B) + rl * RS + c;
        *(uint4*)dsth = *(const uint4*)(Qh_g + (size_t)(s0 + r) * DH + c);
        *(uint4*)dstl = *(const uint4*)(Ql_g + (size_t)(s0 + r) * DH + c);
    }
    __syncthreads();

    uint32_t Ah[4][4], Al[4][4];
    {
        uint32_t half_off = (wid < 4) ? 0u : (uint32_t)(2 * AT_TILE_B);
        int rl = (wid & 3) * 16 + (sel & 1) * 8 + l7;
        uint32_t qoff = aS + half_off + (uint32_t)(rl * RSB + (sel >> 1) * 16);
#pragma unroll
        for (int u = 0; u < 4; u++) {
            ldsm4(Ah[u], qoff + u * 32);
            ldsm4(Al[u], qoff + u * 32 + AT_TILE_B);
        }
    }
    const int bq0 = bkp[s0 + wid * 16 + qid];
    const int bq1 = bkp[s0 + wid * 16 + qid + 8];
    __syncthreads();   // done reading Q staging before prefetch overwrites

    float O[8][4];
#pragma unroll
    for (int j = 0; j < 8; j++)
#pragma unroll
        for (int k = 0; k < 4; k++) O[j][k] = 0.f;
    float m0 = -INFINITY, m1 = -INFINITY, l0 = 0.f, l1 = 0.f;

    const uint32_t khl = (sel < 2) ? 0u : (uint32_t)AT_TILE_B;
    const uint32_t kb_off = khl + l7 * RSB + (sel & 1) * 16;
    const uint32_t vhl = (sel < 2) ? (uint32_t)(2 * AT_TILE_B)
                                   : (uint32_t)(3 * AT_TILE_B);
    const uint32_t vb_off = vhl + (l7 + (sel & 1) * 8) * RSB;

    auto prefetch = [&](int st, int t0) {
#pragma unroll
        for (int i = tid; i < 512; i += 256) {
            int r = i >> 3, c = (i & 7) << 3;
            size_t go = (size_t)(t0 + r) * DH + c;
            uint32_t so = aS + st * AT_STAGE_B + (r * RS + c) * 2;
            cpa16(so,                 Qh_g + go);
            cpa16(so + AT_TILE_B,     Ql_g + go);
            cpa16(so + 2 * AT_TILE_B, Vh_g + go);
            cpa16(so + 3 * AT_TILE_B, Vl_g + go);
        }
        if (tid < 64)
            cpa4(aS + AT_BK_OFF + (st * 64 + tid) * 4, bkp + t0 + tid);
    };

    prefetch(0, 0);
    CP_COMMIT();

    for (int it = 0; it < S_ / 64; it++) {
        if (it + 1 < S_ / 64) {
            prefetch((it + 1) & 1, (it + 1) * 64);
            CP_COMMIT();
            cp_wait<1>();
        } else {
            cp_wait<0>();
        }
        __syncthreads();

        const int st = it & 1;
        const uint32_t stB = aS + st * AT_STAGE_B;
        const int* bks = bkArr + st * 64;

        // ---- S = Q K^T (x3 split, groups of 4 accumulators) ----
        float C[8][4];
#pragma unroll
        for (int j = 0; j < 8; j++)
#pragma unroll
            for (int k = 0; k < 4; k++) C[j][k] = 0.f;

#pragma unroll
        for (int u = 0; u < 4; u++) {
#pragma unroll
            for (int g = 0; g < 2; g++) {
                uint32_t kb[4][4];
#pragma unroll
                for (int j4 = 0; j4 < 4; j4++)
                    ldsm4(kb[j4], stB + kb_off + (g * 4 + j4) * (8 * RSB)
                                  + u * 32);
#pragma unroll
                for (int j4 = 0; j4 < 4; j4++)
                    mma16816(C[g * 4 + j4], Ah[u], kb[j4][0], kb[j4][1]);
#pragma unroll
                for (int j4 = 0; j4 < 4; j4++)
                    mma16816(C[g * 4 + j4], Al[u], kb[j4][0], kb[j4][1]);
#pragma unroll
                for (int j4 = 0; j4 < 4; j4++)
                    mma16816(C[g * 4 + j4], Ah[u], kb[j4][2], kb[j4][3]);
            }
        }

        // ---- coeff (log2-folded) + online softmax (exp2) ----
        float rmax0 = -INFINITY, rmax1 = -INFINITY;
#pragma unroll
        for (int j = 0; j < 8; j++) {
            int tcol = 8 * j + 2 * l2;
            int bk0 = bks[tcol], bk1 = bks[tcol + 1];
            float cf00 = (bq0 == bk0) ? CF_SAME : CF_DIFF;
            float cf01 = (bq0 == bk1) ? CF_SAME : CF_DIFF;
            float cf10 = (bq1 == bk0) ? CF_SAME : CF_DIFF;
            float cf11 = (bq1 == bk1) ? CF_SAME : CF_DIFF;
            C[j][0] *= cf00; C[j][1] *= cf01;
            C[j][2] *= cf10; C[j][3] *= cf11;
            rmax0 = fmaxf(rmax0, fmaxf(C[j][0], C[j][1]));
            rmax1 = fmaxf(rmax1, fmaxf(C[j][2], C[j][3]));
        }
        rmax0 = fmaxf(rmax0, __shfl_xor_sync(0xffffffffu, rmax0, 1));
        rmax0 = fmaxf(rmax0, __shfl_xor_sync(0xffffffffu, rmax0, 2));
        rmax1 = fmaxf(rmax1, __shfl_xor_sync(0xffffffffu, rmax1, 1));
        rmax1 = fmaxf(rmax1, __shfl_xor_sync(0xffffffffu, rmax1, 2));

        float mn0 = fmaxf(m0, rmax0);
        float mn1 = fmaxf(m1, rmax1);
        float corr0 = exp2f(m0 - mn0);
        float corr1 = exp2f(m1 - mn1);
        m0 = mn0; m1 = mn1;

        float sum0 = 0.f, sum1 = 0.f;
#pragma unroll
        for (int j = 0; j < 8; j++) {
            C[j][0] = exp2f(C[j][0] - mn0);
            C[j][1] = exp2f(C[j][1] - mn0);
            C[j][2] = exp2f(C[j][2] - mn1);
            C[j][3] = exp2f(C[j][3] - mn1);
            sum0 += C[j][0] + C[j][1];
            sum1 += C[j][2] + C[j][3];
        }
        sum0 += __shfl_xor_sync(0xffffffffu, sum0, 1);
        sum0 += __shfl_xor_sync(0xffffffffu, sum0, 2);
        sum1 += __shfl_xor_sync(0xffffffffu, sum1, 1);
        sum1 += __shfl_xor_sync(0xffffffffu, sum1, 2);
        l0 = l0 * corr0 + sum0;
        l1 = l1 * corr1 + sum1;

#pragma unroll
        for (int j = 0; j < 8; j++) {
            O[j][0] *= corr0; O[j][1] *= corr0;
            O[j][2] *= corr1; O[j][3] *= corr1;
        }

        // ---- O += P V (x3 split, groups of 2 to bound registers) ----
#pragma unroll
        for (int u = 0; u < 4; u++) {
            uint32_t ph[4], pl[4];
#pragma unroll
            for (int half = 0; half < 2; half++) {
                const float* cc = C[2 * u + half];
                uint32_t h0 = packbf(cc[0], cc[1]);
                uint32_t h1 = packbf(cc[2], cc[3]);
                float r00 = cc[0] - __uint_as_float(h0 << 16);
                float r01 = cc[1] - __uint_as_float(h0 & 0xFFFF0000u);
                float r10 = cc[2] - __uint_as_float(h1 << 16);
                float r11 = cc[3] - __uint_as_float(h1 & 0xFFFF0000u);
                ph[2 * half]     = h0;
                ph[2 * half + 1] = h1;
                pl[2 * half]     = packbf(r00, r01);
                pl[2 * half + 1] = packbf(r10, r11);
            }
#pragma unroll
            for (int g = 0; g < 4; g++) {
                uint32_t vb[2][4];
#pragma unroll
                for (int j2 = 0; j2 < 2; j2++)
                    ldsm4t(vb[j2], stB + vb_off + u * (16 * RSB)
                                   + (g * 2 + j2) * 16);
#pragma unroll
                for (int j2 = 0; j2 < 2; j2++)
                    mma16816(O[g * 2 + j2], ph, vb[j2][0], vb[j2][1]);
#pragma unroll
                for (int j2 = 0; j2 < 2; j2++)
                    mma16816(O[g * 2 + j2], pl, vb[j2][0], vb[j2][1]);
#pragma unroll
                for (int j2 = 0; j2 < 2; j2++)
                    mma16816(O[g * 2 + j2], ph, vb[j2][2], vb[j2][3]);
            }
        }
        __syncthreads();
    }

    const float inv0 = 1.f / l0;
    const float inv1 = 1.f / l1;
    const int srow0 = s0 + wid * 16 + qid;
    const int srow1 = srow0 + 8;
#pragma unroll
    for (int jd = 0; jd < 8; jd++) {
        int d = 8 * jd + 2 * l2;
        float* p0 = out + (((size_t)(b * S_ + srow0)) * H_ + h) * DH + d;
        float* p1 = out + (((size_t)(b * S_ + srow1)) * H_ + h) * DH + d;
        *(float2*)p0 = make_float2(O[jd][0] * inv0, O[jd][1] * inv0);
        *(float2*)p1 = make_float2(O[jd][2] * inv1, O[jd][3] * inv1);
    }
}

// ---------------------------------------------------------------------------
extern "C" void kernel_launch(void* const* d_in, const int* in_sizes, int n_in,
                              void* d_out, int out_size)
{
    const float* x  = (const float*)d_in[0];
    const float* Wq = (const float*)d_in[1];
    const float* bq = (const float*)d_in[2];
    const float* Wv = (const float*)d_in[3];
    const float* bv = (const float*)d_in[4];
    const float* hp = (const float*)d_in[5];
    float* out = (float*)d_out;

    split_kernel<<<6144, 256>>>(x, Wq, Wv);
    whp_kernel<<<dim3(4, 96), 256>>>(Wq, bq, hp);

    const size_t bsmem = (size_t)(BK_B * 68 + BK_B * 96) * sizeof(float);
    cudaFuncSetAttribute(bucket_kernel,
                         cudaFuncAttributeMaxDynamicSharedMemorySize, (int)bsmem);
    bucket_kernel<<<64, 256, bsmem>>>(x);

    cudaFuncSetAttribute(proj_tc_kernel,
                         cudaFuncAttributeMaxDynamicSharedMemorySize,
                         2 * PJ_STAGE_B);
    proj_tc_kernel<<<dim3(8, 32, 2), 256, 2 * PJ_STAGE_B>>>(bq, bv);

    cudaFuncSetAttribute(attn_kernel,
                         cudaFuncAttributeMaxDynamicSharedMemorySize, AT_SMEM);
    attn_kernel<<<dim3(S_ / 128, B_ * H_), 256, AT_SMEM>>>(out);
}

// round 15
// speedup vs baseline: 1.0919x; 1.0919x over previous
#include <cuda_runtime.h>
#include <cuda_bf16.h>
#include <math.h>
#include <stdint.h>

#define B_ 2
#define S_ 2048
#define E_ 1024
#define H_ 16
#define DH 64

// Scratch (device globals — no allocation allowed)
__device__ __nv_bfloat16 g_xh[(size_t)B_ * S_ * E_];
__device__ __nv_bfloat16 g_xl[(size_t)B_ * S_ * E_];
__device__ __nv_bfloat16 g_Wqh[(size_t)E_ * E_];
__device__ __nv_bfloat16 g_Wql[(size_t)E_ * E_];
__device__ __nv_bfloat16 g_Wvh[(size_t)E_ * E_];
__device__ __nv_bfloat16 g_Wvl[(size_t)E_ * E_];
__device__ __nv_bfloat16 g_Qh[(size_t)B_ * H_ * S_ * DH];
__device__ __nv_bfloat16 g_Ql[(size_t)B_ * H_ * S_ * DH];
__device__ __nv_bfloat16 g_Vh[(size_t)B_ * H_ * S_ * DH];
__device__ __nv_bfloat16 g_Vl[(size_t)B_ * H_ * S_ * DH];
__device__ float g_Whp[(size_t)E_ * 96];     // [e][h*6+n]
__device__ float g_cbias[96];
__device__ int   g_bkt[B_ * H_ * S_];

typedef unsigned long long u64;
union F2 { u64 u; float2 f; };

__device__ __forceinline__ u64 dup2(float x) {
    u64 r; asm("mov.b64 %0,{%1,%1};" : "=l"(r) : "f"(x)); return r;
}
__device__ __forceinline__ void fma2(u64& d, u64 a, u64 b) {
    asm("fma.rn.f32x2 %0,%1,%2,%3;" : "=l"(d) : "l"(a), "l"(b), "l"(d));
}
__device__ __forceinline__ void ldsm4(uint32_t* r, uint32_t a) {
    asm volatile("ldmatrix.sync.aligned.m8n8.x4.shared.b16 {%0,%1,%2,%3},[%4];"
                 : "=r"(r[0]), "=r"(r[1]), "=r"(r[2]), "=r"(r[3]) : "r"(a));
}
__device__ __forceinline__ void ldsm4t(uint32_t* r, uint32_t a) {
    asm volatile("ldmatrix.sync.aligned.m8n8.x4.trans.shared.b16 {%0,%1,%2,%3},[%4];"
                 : "=r"(r[0]), "=r"(r[1]), "=r"(r[2]), "=r"(r[3]) : "r"(a));
}
__device__ __forceinline__ void mma16816(float* c, const uint32_t* a,
                                         uint32_t b0, uint32_t b1) {
    asm volatile(
        "mma.sync.aligned.m16n8k16.row.col.f32.bf16.bf16.f32 "
        "{%0,%1,%2,%3},{%4,%5,%6,%7},{%8,%9},{%0,%1,%2,%3};"
        : "+f"(c[0]), "+f"(c[1]), "+f"(c[2]), "+f"(c[3])
        : "r"(a[0]), "r"(a[1]), "r"(a[2]), "r"(a[3]), "r"(b0), "r"(b1));
}
__device__ __forceinline__ uint32_t packbf(float lo, float hi) {
    uint32_t r; asm("cvt.rn.bf16x2.f32 %0,%1,%2;" : "=r"(r) : "f"(hi), "f"(lo));
    return r;
}
__device__ __forceinline__ void cpa16(uint32_t dst, const void* src) {
    asm volatile("cp.async.cg.shared.global [%0],[%1],16;" :: "r"(dst), "l"(src));
}
__device__ __forceinline__ void cpa4(uint32_t dst, const void* src) {
    asm volatile("cp.async.ca.shared.global [%0],[%1],4;" :: "r"(dst), "l"(src));
}
#define CP_COMMIT() asm volatile("cp.async.commit_group;")
template <int N>
__device__ __forceinline__ void cp_wait() {
    asm volatile("cp.async.wait_group %0;" :: "n"(N));
}

// ---------------------------------------------------------------------------
// Split x, Wq, Wv into bf16 hi/lo pairs. 8 floats per thread (2 x float4).
// ---------------------------------------------------------------------------
__global__ __launch_bounds__(256)
void split_kernel(const float* __restrict__ x, const float* __restrict__ Wq,
                  const float* __restrict__ Wv)
{
    size_t idx8 = (size_t)blockIdx.x * 256 + threadIdx.x;
    size_t flat = idx8 * 8;
    const float* src; __nv_bfloat16* dh; __nv_bfloat16* dl; size_t off;
    const size_t NX = (size_t)B_ * S_ * E_;
    const size_t NW = (size_t)E_ * E_;
    if (flat < NX)            { src = x;  dh = g_xh;  dl = g_xl;  off = flat; }
    else if (flat < NX + NW)  { src = Wq; dh = g_Wqh; dl = g_Wql; off = flat - NX; }
    else                      { src = Wv; dh = g_Wvh; dl = g_Wvl; off = flat - NX - NW; }

#pragma unroll
    for (int half = 0; half < 2; half++) {
        float4 v = *(const float4*)(src + off + half * 4);
        float vv[4] = {v.x, v.y, v.z, v.w};
        __align__(8) __nv_bfloat16 hi[4], lo[4];
#pragma unroll
        for (int j = 0; j < 4; j++) {
            hi[j] = __float2bfloat16(vv[j]);
            lo[j] = __float2bfloat16(vv[j] - __bfloat162float(hi[j]));
        }
        *(uint2*)(dh + off + half * 4) = *(const uint2*)hi;
        *(uint2*)(dl + off + half * 4) = *(const uint2*)lo;
    }
}

// ---------------------------------------------------------------------------
// Whp[e][h*6+n] = sum_d Wq[h*64+d][e] * hp[d][n]  ;  cbias[hn] too.
// ---------------------------------------------------------------------------
__global__ __launch_bounds__(256)
void whp_kernel(const float* __restrict__ Wq, const float* __restrict__ bq,
                const float* __restrict__ hp)
{
    const int hn = blockIdx.y;
    const int h = hn / 6, n = hn % 6;
    const int e = blockIdx.x * 256 + threadIdx.x;
    float acc = 0.f;
#pragma unroll 8
    for (int d = 0; d < 64; d++)
        acc = fmaf(Wq[(size_t)(h * 64 + d) * E_ + e], __ldg(hp + d * 6 + n), acc);
    g_Whp[(size_t)e * 96 + hn] = acc;
    if (blockIdx.x == 0 && threadIdx.x == 0) {
        float cb = hp[64 * 6 + n];
        for (int d = 0; d < 64; d++)
            cb = fmaf(bq[h * 64 + d], hp[d * 6 + n], cb);
        g_cbias[hn] = cb;
    }
}

// ---------------------------------------------------------------------------
// Bucket GEMM (fp32 f32x2): proj[m][hn] = x @ Whp + cbias; sign bits.
// ---------------------------------------------------------------------------
#define BK_B 128
__global__ __launch_bounds__(256)
void bucket_kernel(const float* __restrict__ x)
{
    extern __shared__ float bsm[];
    float* sx = bsm;                 // [BK_B][68]
    float* sw = bsm + BK_B * 68;     // [BK_B][96]

    const int tid = threadIdx.x;
    const int tx = tid & 31;
    const int ty = tid >> 5;
    const int m0 = blockIdx.x * 64;

    u64 acc[4][3];
#pragma unroll
    for (int p = 0; p < 4; p++)
#pragma unroll
        for (int c = 0; c < 3; c++) acc[p][c] = dup2(g_cbias[tx + 32 * c]);

    for (int k0 = 0; k0 < E_; k0 += BK_B) {
#pragma unroll
        for (int it = 0; it < 8; it++) {
            int idx = it * 256 + tid;
            int r = idx >> 5;
            int c4 = (idx & 31) << 2;
            float4 v = *(const float4*)(x + (size_t)(m0 + r) * E_ + k0 + c4);
            sx[(c4 + 0) * 68 + r] = v.x; sx[(c4 + 1) * 68 + r] = v.y;
            sx[(c4 + 2) * 68 + r] = v.z; sx[(c4 + 3) * 68 + r] = v.w;
        }
#pragma unroll
        for (int it = 0; it < 12; it++) {
            int u4 = it * 256 + tid;
            *(uint4*)(sw + u4 * 4) =
                *(const uint4*)(g_Whp + (size_t)k0 * 96 + u4 * 4);
        }
        __syncthreads();

#pragma unroll 4
        for (int k = 0; k < BK_B; k++) {
            ulonglong2 x01 = *(const ulonglong2*)(sx + k * 68 + 8 * ty);
            ulonglong2 x23 = *(const ulonglong2*)(sx + k * 68 + 8 * ty + 4);
            u64 xp[4] = {x01.x, x01.y, x23.x, x23.y};
            u64 w0 = dup2(sw[k * 96 + tx]);
            u64 w1 = dup2(sw[k * 96 + tx + 32]);
            u64 w2 = dup2(sw[k * 96 + tx + 64]);
#pragma unroll
            for (int p = 0; p < 4; p++) {
                fma2(acc[p][0], xp[p], w0);
                fma2(acc[p][1], xp[p], w1);
                fma2(acc[p][2], xp[p], w2);
            }
        }
        __syncthreads();
    }

    float* sproj = sx;
#pragma unroll
    for (int p = 0; p < 4; p++) {
#pragma unroll
        for (int c = 0; c < 3; c++) {
            F2 u; u.u = acc[p][c];
            sproj[(8 * ty + 2 * p) * 96 + tx + 32 * c]     = u.f.x;
            sproj[(8 * ty + 2 * p + 1) * 96 + tx + 32 * c] = u.f.y;
        }
    }
    __syncthreads();

#pragma unroll
    for (int u = 0; u < 4; u++) {
        int o = u * 256 + tid;
        int row = o >> 4, h = o & 15;
        int bucket = 0;
#pragma unroll
        for (int n = 0; n < 6; n++)
            if (sproj[row * 96 + h * 6 + n] >= 0.f) bucket |= (1 << n);
        int m = m0 + row;
        int b = m >> 11, s = m & (S_ - 1);
        g_bkt[(b * H_ + h) * S_ + s] = bucket;
    }
}

// ---------------------------------------------------------------------------
// Tensor-core projection GEMM (bf16 x3, mma.sync), 2-stage cp.async pipeline.
// (unchanged — measured at the legacy-HMMA ceiling, 192 us)
// ---------------------------------------------------------------------------
#define PST 40
#define PJ_TILE_B (128 * PST * 2)          // 10240 B per array
#define PJ_STAGE_B (4 * PJ_TILE_B)         // 40960 B per stage

__global__ __launch_bounds__(256, 2)
void proj_tc_kernel(const float* __restrict__ bq, const float* __restrict__ bv)
{
    extern __shared__ char psm[];
    const uint32_t aS = (uint32_t)__cvta_generic_to_shared(psm);

    const int z = blockIdx.z;
    const __nv_bfloat16* Bh_g = z ? g_Wvh : g_Wqh;
    const __nv_bfloat16* Bl_g = z ? g_Wvl : g_Wql;
    const float* bias = z ? bv : bq;
    __nv_bfloat16* Hh = z ? g_Vh : g_Qh;
    __nv_bfloat16* Hl = z ? g_Vl : g_Ql;

    const int tid = threadIdx.x;
    const int wid = tid >> 5, lane = tid & 31;
    const int qid = lane >> 2, l2 = lane & 3;
    const int sel = lane >> 3, l7 = lane & 7;
    const int wm = wid & 3, wn = wid >> 2;
    const int m0 = blockIdx.y << 7;
    const int n0 = blockIdx.x << 7;

    const int r_ld[2]  = { (tid * 2) >> 2, (tid * 2 + 1) >> 2 };
    const int cu_ld[2] = { ((tid * 2) & 3) << 3, ((tid * 2 + 1) & 3) << 3 };

    float C[2][8][4];
#pragma unroll
    for (int a = 0; a < 2; a++)
#pragma unroll
        for (int j = 0; j < 8; j++)
#pragma unroll
            for (int t = 0; t < 4; t++) C[a][j][t] = 0.f;

    const uint32_t aoff = (uint32_t)((wm * 32 + (sel & 1) * 8 + l7) * (PST * 2)
                                     + (sel >> 1) * 16);
    const uint32_t bhl = (sel < 2) ? (2 * PJ_TILE_B) : (3 * PJ_TILE_B);
    const uint32_t boff = bhl + (wn * 64 + l7) * (PST * 2) + (sel & 1) * 16;

    auto prefetch = [&](int st, int k0) {
#pragma unroll
        for (int p = 0; p < 2; p++) {
            int r = r_ld[p], cu = cu_ld[p];
            size_t gx = (size_t)(m0 + r) * E_ + k0 + cu;
            size_t gw = (size_t)(n0 + r) * E_ + k0 + cu;
            uint32_t so = aS + st * PJ_STAGE_B + (r * PST + cu) * 2;
            cpa16(so,                 g_xh + gx);
            cpa16(so + PJ_TILE_B,     g_xl + gx);
            cpa16(so + 2 * PJ_TILE_B, Bh_g + gw);
            cpa16(so + 3 * PJ_TILE_B, Bl_g + gw);
        }
    };

    prefetch(0, 0);
    CP_COMMIT();

    for (int kt = 0; kt < 32; kt++) {
        if (kt + 1 < 32) {
            prefetch((kt + 1) & 1, (kt + 1) * 32);
            CP_COMMIT();
            cp_wait<1>();
        } else {
            cp_wait<0>();
        }
        __syncthreads();

        const uint32_t stB = aS + (kt & 1) * PJ_STAGE_B;
#pragma unroll
        for (int kk = 0; kk < 2; kk++) {
            uint32_t Ahf[2][4], Alf[2][4];
#pragma unroll
            for (int a = 0; a < 2; a++) {
                uint32_t ra = stB + aoff + a * 16 * (PST * 2) + kk * 32;
                ldsm4(Ahf[a], ra);
                ldsm4(Alf[a], ra + PJ_TILE_B);
            }
#pragma unroll
            for (int j = 0; j < 8; j++) {
                uint32_t bb[4];
                ldsm4(bb, stB + boff + j * 8 * (PST * 2) + kk * 32);
#pragma unroll
                for (int a = 0; a < 2; a++) {
                    mma16816(C[a][j], Ahf[a], bb[0], bb[1]);
                    mma16816(C[a][j], Alf[a], bb[0], bb[1]);
                    mma16816(C[a][j], Ahf[a], bb[2], bb[3]);
                }
            }
        }
        __syncthreads();
    }

#pragma unroll
    for (int a = 0; a < 2; a++) {
        int mrow = m0 + wm * 32 + a * 16 + qid;
#pragma unroll
        for (int j = 0; j < 8; j++) {
            int n = n0 + wn * 64 + j * 8 + 2 * l2;
            int h = n >> 6, d = n & 63;
            float b0 = bias[n], b1 = bias[n + 1];
#pragma unroll
            for (int half = 0; half < 2; half++) {
                int m = mrow + half * 8;
                int b = m >> 11, s = m & (S_ - 1);
                size_t off = (((size_t)(b * H_ + h)) * S_ + s) * DH + d;
                float v0 = C[a][j][2 * half + 0] + b0;
                float v1 = C[a][j][2 * half + 1] + b1;
                uint32_t hi = packbf(v0, v1);
                float l0 = v0 - __uint_as_float(hi << 16);
                float l1 = v1 - __uint_as_float(hi & 0xFFFF0000u);
                *(uint32_t*)(Hh + off) = hi;
                *(uint32_t*)(Hl + off) = packbf(l0, l1);
            }
        }
    }
}

// ---------------------------------------------------------------------------
// Tensor-core flash attention (R13 config: s-tile 64, 128 threads, 3 CTAs/SM,
// 2-stage cp.async pipeline, group-of-4 staging) + exp2-folded coefficients.
// ---------------------------------------------------------------------------
#define RS 72
#define RSB 144
#define AT_TILE_B (64 * RS * 2)            // 9216 B
#define AT_STAGE_B (4 * AT_TILE_B)         // 36864 B
#define AT_BK_OFF (2 * AT_STAGE_B)         // 73728 B
#define AT_SMEM (AT_BK_OFF + 2 * 64 * 4)   // 74240 B (x3 = 222.7 KB/SM)
// coeff * log2(e):  (63/32)*log2e, (62/32)*log2e
#define CF_SAME 2.84030586f
#define CF_DIFF 2.79522164f

__global__ __launch_bounds__(128, 3)
void attn_kernel(float* __restrict__ out)
{
    extern __shared__ char asm_[];
    const uint32_t aS = (uint32_t)__cvta_generic_to_shared(asm_);
    __nv_bfloat16* sK0h = (__nv_bfloat16*)asm_;
    int* bkArr = (int*)(asm_ + AT_BK_OFF);

    const int tid = threadIdx.x;
    const int wid = tid >> 5, lane = tid & 31;
    const int qid = lane >> 2;
    const int l2  = lane & 3;
    const int sel = lane >> 3, l7 = lane & 7;

    const int bh = blockIdx.y;
    const int b = bh >> 4, h = bh & 15;
    const int s0 = blockIdx.x << 6;
    const __nv_bfloat16* Qh_g = g_Qh + (size_t)bh * S_ * DH;
    const __nv_bfloat16* Ql_g = g_Ql + (size_t)bh * S_ * DH;
    const __nv_bfloat16* Vh_g = g_Vh + (size_t)bh * S_ * DH;
    const __nv_bfloat16* Vl_g = g_Vl + (size_t)bh * S_ * DH;
    const int* bkp = g_bkt + bh * S_;

    // ---- stage Q tile into stage-0 region, extract A fragments ----
#pragma unroll
    for (int i = tid; i < 512; i += 128) {
        int r = i >> 3, c = (i & 7) << 3;
        *(uint4*)(sK0h + r * RS + c) =
            *(const uint4*)(Qh_g + (size_t)(s0 + r) * DH + c);
        *(uint4*)((__nv_bfloat16*)(asm_ + AT_TILE_B) + r * RS + c) =
            *(const uint4*)(Ql_g + (size_t)(s0 + r) * DH + c);
    }
    __syncthreads();

    uint32_t Ah[4][4], Al[4][4];
    {
        uint32_t qoff = aS + (uint32_t)((wid * 16 + (sel & 1) * 8 + l7) * RSB
                                        + (sel >> 1) * 16);
#pragma unroll
        for (int u = 0; u < 4; u++) {
            ldsm4(Ah[u], qoff + u * 32);
            ldsm4(Al[u], qoff + u * 32 + AT_TILE_B);
        }
    }
    const int bq0 = bkp[s0 + wid * 16 + qid];
    const int bq1 = bkp[s0 + wid * 16 + qid + 8];
    __syncthreads();

    float O[8][4];
#pragma unroll
    for (int j = 0; j < 8; j++)
#pragma unroll
        for (int k = 0; k < 4; k++) O[j][k] = 0.f;
    float m0 = -INFINITY, m1 = -INFINITY, l0 = 0.f, l1 = 0.f;

    const uint32_t khl = (sel < 2) ? 0u : (uint32_t)AT_TILE_B;
    const uint32_t kb_off = khl + l7 * RSB + (sel & 1) * 16;
    const uint32_t vhl = (sel < 2) ? (uint32_t)(2 * AT_TILE_B)
                                   : (uint32_t)(3 * AT_TILE_B);
    const uint32_t vb_off = vhl + (l7 + (sel & 1) * 8) * RSB;

    auto prefetch = [&](int st, int t0) {
#pragma unroll
        for (int i = tid; i < 512; i += 128) {
            int r = i >> 3, c = (i & 7) << 3;
            size_t go = (size_t)(t0 + r) * DH + c;
            uint32_t so = aS + st * AT_STAGE_B + (r * RS + c) * 2;
            cpa16(so,                 Qh_g + go);
            cpa16(so + AT_TILE_B,     Ql_g + go);
            cpa16(so + 2 * AT_TILE_B, Vh_g + go);
            cpa16(so + 3 * AT_TILE_B, Vl_g + go);
        }
        if (tid < 64)
            cpa4(aS + AT_BK_OFF + (st * 64 + tid) * 4, bkp + t0 + tid);
    };

    prefetch(0, 0);
    CP_COMMIT();

    for (int it = 0; it < S_ / 64; it++) {
        if (it + 1 < S_ / 64) {
            prefetch((it + 1) & 1, (it + 1) * 64);
            CP_COMMIT();
            cp_wait<1>();
        } else {
            cp_wait<0>();
        }
        __syncthreads();

        const int st = it & 1;
        const uint32_t stB = aS + st * AT_STAGE_B;
        const int* bks = bkArr + st * 64;

        // ---- S = Q K^T (x3 split, groups of 4 accumulators) ----
        float C[8][4];
#pragma unroll
        for (int j = 0; j < 8; j++)
#pragma unroll
            for (int k = 0; k < 4; k++) C[j][k] = 0.f;

#pragma unroll
        for (int u = 0; u < 4; u++) {
#pragma unroll
            for (int g = 0; g < 2; g++) {
                uint32_t kb[4][4];
#pragma unroll
                for (int j4 = 0; j4 < 4; j4++)
                    ldsm4(kb[j4], stB + kb_off + (g * 4 + j4) * (8 * RSB)
                                  + u * 32);
#pragma unroll
                for (int j4 = 0; j4 < 4; j4++)
                    mma16816(C[g * 4 + j4], Ah[u], kb[j4][0], kb[j4][1]);
#pragma unroll
                for (int j4 = 0; j4 < 4; j4++)
                    mma16816(C[g * 4 + j4], Al[u], kb[j4][0], kb[j4][1]);
#pragma unroll
                for (int j4 = 0; j4 < 4; j4++)
                    mma16816(C[g * 4 + j4], Ah[u], kb[j4][2], kb[j4][3]);
            }
        }

        // ---- coeff (log2-folded) + online softmax (exp2) ----
        float rmax0 = -INFINITY, rmax1 = -INFINITY;
#pragma unroll
        for (int j = 0; j < 8; j++) {
            int tcol = 8 * j + 2 * l2;
            int bk0 = bks[tcol], bk1 = bks[tcol + 1];
            float cf00 = (bq0 == bk0) ? CF_SAME : CF_DIFF;
            float cf01 = (bq0 == bk1) ? CF_SAME : CF_DIFF;
            float cf10 = (bq1 == bk0) ? CF_SAME : CF_DIFF;
            float cf11 = (bq1 == bk1) ? CF_SAME : CF_DIFF;
            C[j][0] *= cf00; C[j][1] *= cf01;
            C[j][2] *= cf10; C[j][3] *= cf11;
            rmax0 = fmaxf(rmax0, fmaxf(C[j][0], C[j][1]));
            rmax1 = fmaxf(rmax1, fmaxf(C[j][2], C[j][3]));
        }
        rmax0 = fmaxf(rmax0, __shfl_xor_sync(0xffffffffu, rmax0, 1));
        rmax0 = fmaxf(rmax0, __shfl_xor_sync(0xffffffffu, rmax0, 2));
        rmax1 = fmaxf(rmax1, __shfl_xor_sync(0xffffffffu, rmax1, 1));
        rmax1 = fmaxf(rmax1, __shfl_xor_sync(0xffffffffu, rmax1, 2));

        float mn0 = fmaxf(m0, rmax0);
        float mn1 = fmaxf(m1, rmax1);
        float corr0 = exp2f(m0 - mn0);
        float corr1 = exp2f(m1 - mn1);
        m0 = mn0; m1 = mn1;

        float sum0 = 0.f, sum1 = 0.f;
#pragma unroll
        for (int j = 0; j < 8; j++) {
            C[j][0] = exp2f(C[j][0] - mn0);
            C[j][1] = exp2f(C[j][1] - mn0);
            C[j][2] = exp2f(C[j][2] - mn1);
            C[j][3] = exp2f(C[j][3] - mn1);
            sum0 += C[j][0] + C[j][1];
            sum1 += C[j][2] + C[j][3];
        }
        sum0 += __shfl_xor_sync(0xffffffffu, sum0, 1);
        sum0 += __shfl_xor_sync(0xffffffffu, sum0, 2);
        sum1 += __shfl_xor_sync(0xffffffffu, sum1, 1);
        sum1 += __shfl_xor_sync(0xffffffffu, sum1, 2);
        l0 = l0 * corr0 + sum0;
        l1 = l1 * corr1 + sum1;

#pragma unroll
        for (int j = 0; j < 8; j++) {
            O[j][0] *= corr0; O[j][1] *= corr0;
            O[j][2] *= corr1; O[j][3] *= corr1;
        }

        // ---- O += P V (x3 split, groups of 4 accumulators) ----
#pragma unroll
        for (int u = 0; u < 4; u++) {
            uint32_t ph[4], pl[4];
#pragma unroll
            for (int half = 0; half < 2; half++) {
                const float* cc = C[2 * u + half];
                uint32_t h0 = packbf(cc[0], cc[1]);
                uint32_t h1 = packbf(cc[2], cc[3]);
                float r00 = cc[0] - __uint_as_float(h0 << 16);
                float r01 = cc[1] - __uint_as_float(h0 & 0xFFFF0000u);
                float r10 = cc[2] - __uint_as_float(h1 << 16);
                float r11 = cc[3] - __uint_as_float(h1 & 0xFFFF0000u);
                ph[2 * half]     = h0;
                ph[2 * half + 1] = h1;
                pl[2 * half]     = packbf(r00, r01);
                pl[2 * half + 1] = packbf(r10, r11);
            }
#pragma unroll
            for (int g = 0; g < 2; g++) {
                uint32_t vb[4][4];
#pragma unroll
                for (int j4 = 0; j4 < 4; j4++)
                    ldsm4t(vb[j4], stB + vb_off + u * (16 * RSB)
                                   + (g * 4 + j4) * 16);
#pragma unroll
                for (int j4 = 0; j4 < 4; j4++)
                    mma16816(O[g * 4 + j4], ph, vb[j4][0], vb[j4][1]);
#pragma unroll
                for (int j4 = 0; j4 < 4; j4++)
                    mma16816(O[g * 4 + j4], pl, vb[j4][0], vb[j4][1]);
#pragma unroll
                for (int j4 = 0; j4 < 4; j4++)
                    mma16816(O[g * 4 + j4], ph, vb[j4][2], vb[j4][3]);
            }
        }
        __syncthreads();
    }

    const float inv0 = 1.f / l0;
    const float inv1 = 1.f / l1;
    const int srow0 = s0 + wid * 16 + qid;
    const int srow1 = srow0 + 8;
#pragma unroll
    for (int jd = 0; jd < 8; jd++) {
        int d = 8 * jd + 2 * l2;
        float* p0 = out + (((size_t)(b * S_ + srow0)) * H_ + h) * DH + d;
        float* p1 = out + (((size_t)(b * S_ + srow1)) * H_ + h) * DH + d;
        *(float2*)p0 = make_float2(O[jd][0] * inv0, O[jd][1] * inv0);
        *(float2*)p1 = make_float2(O[jd][2] * inv1, O[jd][3] * inv1);
    }
}

// ---------------------------------------------------------------------------
extern "C" void kernel_launch(void* const* d_in, const int* in_sizes, int n_in,
                              void* d_out, int out_size)
{
    const float* x  = (const float*)d_in[0];
    const float* Wq = (const float*)d_in[1];
    const float* bq = (const float*)d_in[2];
    const float* Wv = (const float*)d_in[3];
    const float* bv = (const float*)d_in[4];
    const float* hp = (const float*)d_in[5];
    float* out = (float*)d_out;

    split_kernel<<<3072, 256>>>(x, Wq, Wv);
    whp_kernel<<<dim3(4, 96), 256>>>(Wq, bq, hp);

    const size_t bsmem = (size_t)(BK_B * 68 + BK_B * 96) * sizeof(float);
    cudaFuncSetAttribute(bucket_kernel,
                         cudaFuncAttributeMaxDynamicSharedMemorySize, (int)bsmem);
    bucket_kernel<<<64, 256, bsmem>>>(x);

    cudaFuncSetAttribute(proj_tc_kernel,
                         cudaFuncAttributeMaxDynamicSharedMemorySize,
                         2 * PJ_STAGE_B);
    proj_tc_kernel<<<dim3(8, 32, 2), 256, 2 * PJ_STAGE_B>>>(bq, bv);

    cudaFuncSetAttribute(attn_kernel,
                         cudaFuncAttributeMaxDynamicSharedMemorySize, AT_SMEM);
    attn_kernel<<<dim3(S_ / 64, B_ * H_), 128, AT_SMEM>>>(out);
}